// round 14
// baseline (speedup 1.0000x reference)
#include <cuda_runtime.h>
#include <cuda_fp16.h>
#include <cstdint>
#include <math.h>

// Fused 3x3 conv via fp16 m16n8k16 MMA with exact Dekker split (3 products,
// fp32-class z) + LIF scan + flag-and-fix.
//
// Round-13 change (on the round-11 451us skeleton, 256 threads):
// pair-interleaved smem planes (old word w -> w<4 ? 2w : 2(w-4)+1, pitch 40)
// make every MMA fragment pair adjacent -> uint2 LDS.64 loads. Per k-tile
// LDS drops 24 -> 12, removing the SMSP LDS-issue bottleneck.
// Plus 3 no-op launches so ncu's skip-5 window lands on the MAIN kernel.
//
// x: [T=8, B=16, Cin=64, 64, 64] f32   w: [64, 64, 3, 3] f32
// out: spikes [8, 16, 64, 64, 64] f32

#define TT 8
#define BB 16
#define NSM 148
#define NUNITS 1024          // 16 b x 64 tiles (16 y-groups x 4 x-groups)
#define PFN 27               // 64*108 / 256 prefetch elements per thread

// word (4B) offsets in dynamic smem; pitch 40 words per row
#define WPLANE_WORDS (576 * 40)           // [tap*64+co][interleaved ci] f16x2
#define INPLANE_WORDS (108 * 40)          // [y*18+x][interleaved ci]
#define SM_WH 0
#define SM_WL WPLANE_WORDS
#define SM_INH (2 * WPLANE_WORDS)
#define SM_INL (2 * WPLANE_WORDS + INPLANE_WORDS)
#define SMEM_WORDS (2 * WPLANE_WORDS + 2 * INPLANE_WORDS)
#define SMEM_BYTES (SMEM_WORDS * 4)       // 218,880 B

#define FLAG_CAP 131072
#define FLAG_DELTA 4e-5f

__device__ int g_cnt;    // zeroed at module load; reset by fix_kernel
__device__ int g_done;
__device__ int g_idx[FLAG_CAP];

// interleaved half-index within a row: row*80 halves, 8-word blocks of 16 ci
__device__ __forceinline__ int ileave_half(int row, int ci) {
    int p  = (ci & 15) >> 1;                      // pair 0..7
    int wo = (p < 4) ? (2 * p) : (2 * (p - 4) + 1);
    return row * 80 + (ci >> 4) * 16 + wo * 2 + (ci & 1);
}

__device__ __forceinline__ void mma16(float* c, uint32_t a0, uint32_t a1,
                                      uint32_t a2, uint32_t a3,
                                      uint32_t b0, uint32_t b1) {
    asm volatile(
        "mma.sync.aligned.m16n8k16.row.col.f32.f16.f16.f32 "
        "{%0,%1,%2,%3}, {%4,%5,%6,%7}, {%8,%9}, {%0,%1,%2,%3};"
        : "+f"(c[0]), "+f"(c[1]), "+f"(c[2]), "+f"(c[3])
        : "r"(a0), "r"(a1), "r"(a2), "r"(a3), "r"(b0), "r"(b1));
}
__device__ __forceinline__ void push_flag(int enc) {
    int i = atomicAdd(&g_cnt, 1);
    if (i < FLAG_CAP) g_idx[i] = enc;
}

__global__ __launch_bounds__(256, 1)
void snn_conv_lif_kernel(const float* __restrict__ x,
                         const float* __restrict__ w,
                         float* __restrict__ out)
{
    extern __shared__ uint32_t smem[];
    uint32_t* whU  = smem + SM_WH;
    uint32_t* wlU  = smem + SM_WL;
    uint32_t* inhU = smem + SM_INH;
    uint32_t* inlU = smem + SM_INL;
    __half* whH  = reinterpret_cast<__half*>(whU);
    __half* wlH  = reinterpret_cast<__half*>(wlU);
    __half* inhH = reinterpret_cast<__half*>(inhU);
    __half* inlH = reinterpret_cast<__half*>(inlU);

    const int tid  = threadIdx.x;
    const int wid  = tid >> 5;
    const int lane = tid & 31;
    const int gid  = lane >> 2;          // 0..7
    const int tig  = lane & 3;           // 0..3

    const int warpM = wid & 3;           // 1 y-row of 16 px
    const int warpN = wid >> 2;          // 32-co half

    // ---- stage weights ONCE: hi/lo planes, interleaved pairs ----
    for (int idx = tid; idx < 64 * 64 * 9; idx += 256) {
        int co  = idx / 576;
        int r   = idx % 576;
        int ci  = r / 9;
        int tap = r % 9;
        float f = w[idx];
        __half h = __float2half_rn(f);
        __half l = __float2half_rn(f - __half2float(h));
        int hidx = ileave_half(tap * 64 + co, ci);
        whH[hidx] = h;
        wlH[hidx] = l;
    }

    // ---- persistent loop over work units ----
    for (int u = blockIdx.x; u < NUNITS; u += NSM) {
        const int b    = u >> 6;
        const int tile = u & 63;
        const int ty0  = (tile >> 2) * 4;    // 16 y-groups of 4 rows
        const int tx0  = (tile & 3) * 16;    // 4 x-groups of 16 cols

        float v[16];
        #pragma unroll
        for (int i = 0; i < 16; ++i) v[i] = 0.0f;

        // ---- direct stage for t=0 (also fences weights on first unit) ----
        {
            const float* xt = x + (size_t)b * (64 * 64 * 64);
            #pragma unroll
            for (int k = 0; k < PFN; ++k) {
                int i   = tid + k * 256;
                int ci  = i / 108;
                int pix = i - ci * 108;
                int tyi = pix / 18;
                int txi = pix - tyi * 18;
                int gy = ty0 + tyi - 1;
                int gx = tx0 + txi - 1;
                float val = 0.0f;
                if ((unsigned)gy < 64u && (unsigned)gx < 64u)
                    val = xt[ci * 4096 + gy * 64 + gx];
                __half h = __float2half_rn(val);
                __half l = __float2half_rn(val - __half2float(h));
                int hidx = ileave_half(pix, ci);
                inhH[hidx] = h;
                inlH[hidx] = l;
            }
        }
        __syncthreads();

        for (int t = 0; t < TT; ++t) {
            // ---- prefetch NEXT timestep's inputs into registers ----
            float pf[PFN];
            if (t < TT - 1) {
                const float* xn = x + (size_t)((t + 1) * BB + b) * (64 * 64 * 64);
                #pragma unroll
                for (int k = 0; k < PFN; ++k) {
                    int i   = tid + k * 256;
                    int ci  = i / 108;
                    int pix = i - ci * 108;
                    int tyi = pix / 18;
                    int txi = pix - tyi * 18;
                    int gy = ty0 + tyi - 1;
                    int gx = tx0 + txi - 1;
                    float val = 0.0f;
                    if ((unsigned)gy < 64u && (unsigned)gx < 64u)
                        val = xn[ci * 4096 + gy * 64 + gx];
                    pf[k] = val;
                }
            }

            // ---- implicit GEMM, fp16 split x3, LDS.64 fragments ----
            float acc[16];
            #pragma unroll
            for (int i = 0; i < 16; ++i) acc[i] = 0.0f;

            #pragma unroll 1
            for (int tap = 0; tap < 9; ++tap) {
                const int ky = tap / 3, kx = tap % 3;

                #pragma unroll
                for (int kb = 0; kb < 4; ++kb) {       // 16 ci per k-tile
                    const int pix = (warpM + ky) * 18 + kx + gid;
                    const int pa2 = pix * 40 + kb * 8 + 2 * tig;
                    const int pb2 = pa2 + 8 * 40;      // pixel x + 8
                    // A fragments: (a0,a2) and (a1,a3) as uint2
                    uint2 hA = *reinterpret_cast<const uint2*>(inhU + pa2);
                    uint2 hB = *reinterpret_cast<const uint2*>(inhU + pb2);
                    uint2 lA = *reinterpret_cast<const uint2*>(inlU + pa2);
                    uint2 lB = *reinterpret_cast<const uint2*>(inlU + pb2);
                    #pragma unroll
                    for (int nt = 0; nt < 4; ++nt) {
                        const int co = warpN * 32 + nt * 8 + gid;
                        const int wi2 = (tap * 64 + co) * 40 + kb * 8 + 2 * tig;
                        uint2 bh = *reinterpret_cast<const uint2*>(whU + wi2);
                        uint2 bl = *reinterpret_cast<const uint2*>(wlU + wi2);
                        mma16(&acc[nt * 4], hA.x, hB.x, hA.y, hB.y, bh.x, bh.y);
                        mma16(&acc[nt * 4], lA.x, lB.x, lA.y, lB.y, bh.x, bh.y);
                        mma16(&acc[nt * 4], hA.x, hB.x, hA.y, hB.y, bl.x, bl.y);
                    }
                }
            }

            // ---- LIF update + near-threshold flagging + spike store ----
            float* obase = out + (size_t)(t * BB + b) * (64 * 4096);
            const int yg = ty0 + warpM;
            #pragma unroll
            for (int nt = 0; nt < 4; ++nt) {
                #pragma unroll
                for (int r = 0; r < 4; ++r) {
                    const int co = warpN * 32 + nt * 8 + 2 * tig + (r & 1);
                    const int xg = tx0 + gid + ((r & 2) ? 8 : 0);
                    const int vi = nt * 4 + r;
                    float z = acc[vi];
                    float vv = v[vi];
                    vv = vv + (z - vv) * 0.5f;   // TAU=2, reference op order
                    if (fabsf(vv - 1.0f) < FLAG_DELTA)
                        push_flag((((b * 64 + co) * 64 + yg) * 64) + xg);
                    float s = (vv >= 1.0f) ? 1.0f : 0.0f;
                    v[vi] = (vv >= 1.0f) ? 0.0f : vv;
                    obase[(size_t)co * 4096 + yg * 64 + xg] = s;
                }
            }

            __syncthreads();   // all MMA reads of input planes done

            // ---- commit prefetched inputs (convert + split + STS) ----
            if (t < TT - 1) {
                #pragma unroll
                for (int k = 0; k < PFN; ++k) {
                    int i   = tid + k * 256;
                    int ci  = i / 108;
                    int pix = i - ci * 108;
                    float val = pf[k];
                    __half h = __float2half_rn(val);
                    __half l = __float2half_rn(val - __half2float(h));
                    int hidx = ileave_half(pix, ci);
                    inhH[hidx] = h;
                    inlH[hidx] = l;
                }
                __syncthreads();
            }
        }
    }
}

// ---------------- flag-and-fix ----------------
// Warp-per-trajectory: exact fp64 conv (lane-split ci + shuffle reduce),
// round z to fp32, reference-identical fp32 LIF. Overwrites all T spikes.
// Last block resets g_cnt/g_done so the captured graph is replay-safe.
__global__ void fix_kernel(const float* __restrict__ x,
                           const float* __restrict__ w,
                           float* __restrict__ out)
{
    int n = g_cnt;
    if (n > FLAG_CAP) n = FLAG_CAP;
    const int lane = threadIdx.x & 31;
    const int wid  = (blockIdx.x * blockDim.x + threadIdx.x) >> 5;
    const int nw   = (gridDim.x * blockDim.x) >> 5;

    for (int i = wid; i < n; i += nw) {
        int e = g_idx[i];
        int xp = e & 63;
        int y  = (e >> 6) & 63;
        int co = (e >> 12) & 63;
        int b  = e >> 18;
        const float* wr = w + co * 576;
        const int ci0 = lane * 2;
        float v = 0.0f;
        for (int t = 0; t < TT; ++t) {
            const float* xt = x + (size_t)(t * BB + b) * (64 * 64 * 64);
            double z = 0.0;
            #pragma unroll
            for (int cc = 0; cc < 2; ++cc) {
                int ci = ci0 + cc;
                #pragma unroll
                for (int ky = 0; ky < 3; ++ky) {
                    int gy = y + ky - 1;
                    if ((unsigned)gy >= 64u) continue;
                    const float* xr = xt + ci * 4096 + gy * 64;
                    const float* wk = wr + ci * 9 + ky * 3;
                    #pragma unroll
                    for (int kx = 0; kx < 3; ++kx) {
                        int gx = xp + kx - 1;
                        if ((unsigned)gx >= 64u) continue;
                        z += (double)xr[gx] * (double)wk[kx];
                    }
                }
            }
            #pragma unroll
            for (int off = 16; off > 0; off >>= 1)
                z += __shfl_down_sync(0xffffffffu, z, off);
            if (lane == 0) {
                float zf = (float)z;
                v = v + (zf - v) * 0.5f;
                float s = (v >= 1.0f) ? 1.0f : 0.0f;
                v = (v >= 1.0f) ? 0.0f : v;
                out[((size_t)(t * BB + b) * 64 + co) * 4096 + y * 64 + xp] = s;
            }
        }
    }

    __syncthreads();
    if (threadIdx.x == 0) {
        __threadfence();
        int d = atomicAdd(&g_done, 1);
        if (d == (int)gridDim.x - 1) {
            g_cnt = 0;
            g_done = 0;
            __threadfence();
        }
    }
}

// No-op spacer so ncu's "-s 5 -c 1" window (launch index 5) lands on the
// MAIN kernel: 5 launches per call -> main at indices 0 mod 5.
__global__ void spacer_kernel() {}

extern "C" void kernel_launch(void* const* d_in, const int* in_sizes, int n_in,
                              void* d_out, int out_size) {
    const float* x  = (const float*)d_in[0];
    const float* w  = (const float*)d_in[1];
    float* out      = (float*)d_out;
    cudaFuncSetAttribute(snn_conv_lif_kernel,
                         cudaFuncAttributeMaxDynamicSharedMemorySize, SMEM_BYTES);
    snn_conv_lif_kernel<<<NSM, 256, SMEM_BYTES>>>(x, w, out);
    fix_kernel<<<256, 256>>>(x, w, out);
    spacer_kernel<<<1, 32>>>();
    spacer_kernel<<<1, 32>>>();
    spacer_kernel<<<1, 32>>>();
}

// round 15
// speedup vs baseline: 1.2787x; 1.2787x over previous
#include <cuda_runtime.h>
#include <cuda_fp16.h>
#include <cstdint>
#include <math.h>

// Fused 3x3 conv via fp16 m16n8k16 MMA with exact Dekker split (3 products,
// fp32-class z) + LIF scan + flag-and-fix.
//
// Round-14: main kernel is the round-11 451us artifact, byte-identical
// (rounds 12/13/14 showed every mainloop perturbation regresses 35-140us).
// Change is confined to the fixer: timestep-parallel fp64 conv (lane = t x
// ci-quarter, shuffle-reduce, lane 0 runs the LIF scan) cuts its serial
// 8-step latency chain ~8x.
//
// x: [T=8, B=16, Cin=64, 64, 64] f32   w: [64, 64, 3, 3] f32
// out: spikes [8, 16, 64, 64, 64] f32

#define TT 8
#define BB 16
#define NSM 148
#define NUNITS 1024          // 16 b x 64 tiles (16 y-groups x 4 x-groups)
#define PFN 27               // 64*108 / 256 prefetch elements per thread

// word (4B) offsets in dynamic smem
#define WPLANE_WORDS (576 * 36)           // [tap*64+co][ci/2] f16x2, pitch 36
#define INPLANE_WORDS (108 * 36)          // [y*18+x][ci/2], 6 rows x 18 cols
#define SM_WH 0
#define SM_WL WPLANE_WORDS
#define SM_INH (2 * WPLANE_WORDS)
#define SM_INL (2 * WPLANE_WORDS + INPLANE_WORDS)
#define SMEM_WORDS (2 * WPLANE_WORDS + 2 * INPLANE_WORDS)
#define SMEM_BYTES (SMEM_WORDS * 4)       // 196,992 B

#define FLAG_CAP 131072
#define FLAG_DELTA 4e-5f

__device__ int g_cnt;    // zeroed at module load; reset by fix_kernel
__device__ int g_done;
__device__ int g_idx[FLAG_CAP];

__device__ __forceinline__ void mma16(float* c, const uint32_t* a,
                                      uint32_t b0, uint32_t b1) {
    asm volatile(
        "mma.sync.aligned.m16n8k16.row.col.f32.f16.f16.f32 "
        "{%0,%1,%2,%3}, {%4,%5,%6,%7}, {%8,%9}, {%0,%1,%2,%3};"
        : "+f"(c[0]), "+f"(c[1]), "+f"(c[2]), "+f"(c[3])
        : "r"(a[0]), "r"(a[1]), "r"(a[2]), "r"(a[3]), "r"(b0), "r"(b1));
}
__device__ __forceinline__ void push_flag(int enc) {
    int i = atomicAdd(&g_cnt, 1);
    if (i < FLAG_CAP) g_idx[i] = enc;
}

__global__ __launch_bounds__(256, 1)
void snn_conv_lif_kernel(const float* __restrict__ x,
                         const float* __restrict__ w,
                         float* __restrict__ out)
{
    extern __shared__ uint32_t smem[];
    uint32_t* whU  = smem + SM_WH;
    uint32_t* wlU  = smem + SM_WL;
    uint32_t* inhU = smem + SM_INH;
    uint32_t* inlU = smem + SM_INL;
    __half* whH  = reinterpret_cast<__half*>(whU);
    __half* wlH  = reinterpret_cast<__half*>(wlU);
    __half* inhH = reinterpret_cast<__half*>(inhU);
    __half* inlH = reinterpret_cast<__half*>(inlU);

    const int tid  = threadIdx.x;
    const int wid  = tid >> 5;
    const int lane = tid & 31;
    const int gid  = lane >> 2;          // 0..7
    const int tig  = lane & 3;           // 0..3

    const int warpM = wid & 3;           // 1 y-row of 16 px
    const int warpN = wid >> 2;          // 32-co half

    // ---- stage weights ONCE: hi/lo half-planes [tap*64+co][ci] ----
    for (int idx = tid; idx < 64 * 64 * 9; idx += 256) {
        int co  = idx / 576;
        int r   = idx % 576;
        int ci  = r / 9;
        int tap = r % 9;
        float f = w[idx];
        __half h = __float2half_rn(f);
        __half l = __float2half_rn(f - __half2float(h));
        int hidx = (tap * 64 + co) * 72 + ci;   // pitch 72 halves
        whH[hidx] = h;
        wlH[hidx] = l;
    }

    // ---- persistent loop over work units ----
    for (int u = blockIdx.x; u < NUNITS; u += NSM) {
        const int b    = u >> 6;
        const int tile = u & 63;
        const int ty0  = (tile >> 2) * 4;    // 16 y-groups of 4 rows
        const int tx0  = (tile & 3) * 16;    // 4 x-groups of 16 cols

        float v[16];
        #pragma unroll
        for (int i = 0; i < 16; ++i) v[i] = 0.0f;

        // ---- direct stage for t=0 (also fences weights on first unit) ----
        {
            const float* xt = x + (size_t)b * (64 * 64 * 64);
            #pragma unroll
            for (int k = 0; k < PFN; ++k) {
                int i   = tid + k * 256;
                int ci  = i / 108;
                int pix = i - ci * 108;
                int tyi = pix / 18;
                int txi = pix - tyi * 18;
                int gy = ty0 + tyi - 1;
                int gx = tx0 + txi - 1;
                float val = 0.0f;
                if ((unsigned)gy < 64u && (unsigned)gx < 64u)
                    val = xt[ci * 4096 + gy * 64 + gx];
                __half h = __float2half_rn(val);
                __half l = __float2half_rn(val - __half2float(h));
                inhH[pix * 72 + ci] = h;
                inlH[pix * 72 + ci] = l;
            }
        }
        __syncthreads();

        for (int t = 0; t < TT; ++t) {
            // ---- prefetch NEXT timestep's inputs into registers ----
            float pf[PFN];
            if (t < TT - 1) {
                const float* xn = x + (size_t)((t + 1) * BB + b) * (64 * 64 * 64);
                #pragma unroll
                for (int k = 0; k < PFN; ++k) {
                    int i   = tid + k * 256;
                    int ci  = i / 108;
                    int pix = i - ci * 108;
                    int tyi = pix / 18;
                    int txi = pix - tyi * 18;
                    int gy = ty0 + tyi - 1;
                    int gx = tx0 + txi - 1;
                    float val = 0.0f;
                    if ((unsigned)gy < 64u && (unsigned)gx < 64u)
                        val = xn[ci * 4096 + gy * 64 + gx];
                    pf[k] = val;
                }
            }

            // ---- implicit GEMM, fp16 split x3: acc[nt*4 + r] ----
            float acc[16];
            #pragma unroll
            for (int i = 0; i < 16; ++i) acc[i] = 0.0f;

            #pragma unroll 1
            for (int tap = 0; tap < 9; ++tap) {
                const int ky = tap / 3, kx = tap % 3;

                #pragma unroll
                for (int kb = 0; kb < 4; ++kb) {       // 16 ci per k-tile
                    const int pix = (warpM + ky) * 18 + kx + gid;
                    const int pa  = pix * 36 + kb * 8 + tig;
                    const int pb  = pa + 8 * 36;       // pixel x + 8
                    uint32_t ah[4], al[4];
                    ah[0] = inhU[pa];
                    ah[1] = inhU[pb];
                    ah[2] = inhU[pa + 4];
                    ah[3] = inhU[pb + 4];
                    al[0] = inlU[pa];
                    al[1] = inlU[pb];
                    al[2] = inlU[pa + 4];
                    al[3] = inlU[pb + 4];
                    #pragma unroll
                    for (int nt = 0; nt < 4; ++nt) {
                        const int co = warpN * 32 + nt * 8 + gid;
                        const int wi = (tap * 64 + co) * 36 + kb * 8 + tig;
                        uint32_t bh0 = whU[wi], bh1 = whU[wi + 4];
                        uint32_t bl0 = wlU[wi], bl1 = wlU[wi + 4];
                        mma16(&acc[nt * 4], ah, bh0, bh1);
                        mma16(&acc[nt * 4], al, bh0, bh1);
                        mma16(&acc[nt * 4], ah, bl0, bl1);
                    }
                }
            }

            // ---- LIF update + near-threshold flagging + spike store ----
            float* obase = out + (size_t)(t * BB + b) * (64 * 4096);
            const int yg = ty0 + warpM;
            #pragma unroll
            for (int nt = 0; nt < 4; ++nt) {
                #pragma unroll
                for (int r = 0; r < 4; ++r) {
                    const int co = warpN * 32 + nt * 8 + 2 * tig + (r & 1);
                    const int xg = tx0 + gid + ((r & 2) ? 8 : 0);
                    const int vi = nt * 4 + r;
                    float z = acc[vi];
                    float vv = v[vi];
                    vv = vv + (z - vv) * 0.5f;   // TAU=2, reference op order
                    if (fabsf(vv - 1.0f) < FLAG_DELTA)
                        push_flag((((b * 64 + co) * 64 + yg) * 64) + xg);
                    float s = (vv >= 1.0f) ? 1.0f : 0.0f;
                    v[vi] = (vv >= 1.0f) ? 0.0f : vv;
                    obase[(size_t)co * 4096 + yg * 64 + xg] = s;
                }
            }

            __syncthreads();   // all MMA reads of input planes done

            // ---- commit prefetched inputs (convert + split + STS) ----
            if (t < TT - 1) {
                #pragma unroll
                for (int k = 0; k < PFN; ++k) {
                    int i   = tid + k * 256;
                    int ci  = i / 108;
                    int pix = i - ci * 108;
                    float val = pf[k];
                    __half h = __float2half_rn(val);
                    __half l = __float2half_rn(val - __half2float(h));
                    inhH[pix * 72 + ci] = h;
                    inlH[pix * 72 + ci] = l;
                }
                __syncthreads();
            }
        }
    }
}

// ---------------- flag-and-fix (timestep-parallel) ----------------
// Warp per trajectory. Lane l: timestep = l>>2, ci-quarter = l&3. Each lane
// accumulates 16 ci x 9 taps in fp64; 2-step shuffle reduce forms z_t on
// lane 4t; lane 0 gathers all 8 z's and runs the reference-identical fp32
// LIF scan. Cuts the fixer's serial latency chain ~8x.
// Last block resets g_cnt/g_done so the captured graph is replay-safe.
__global__ void fix_kernel(const float* __restrict__ x,
                           const float* __restrict__ w,
                           float* __restrict__ out)
{
    int n = g_cnt;
    if (n > FLAG_CAP) n = FLAG_CAP;
    const int lane = threadIdx.x & 31;
    const int wid  = (blockIdx.x * blockDim.x + threadIdx.x) >> 5;
    const int nw   = (gridDim.x * blockDim.x) >> 5;
    const int tl   = lane >> 2;          // this lane's timestep 0..7
    const int sub  = lane & 3;           // ci quarter

    for (int i = wid; i < n; i += nw) {
        int e = g_idx[i];
        int xp = e & 63;
        int y  = (e >> 6) & 63;
        int co = (e >> 12) & 63;
        int b  = e >> 18;
        const float* wr = w + co * 576;
        const float* xt = x + (size_t)(tl * BB + b) * (64 * 64 * 64);

        double z = 0.0;
        #pragma unroll 4
        for (int cc = 0; cc < 16; ++cc) {
            int ci = sub * 16 + cc;
            const float* xc = xt + ci * 4096;
            const float* wc = wr + ci * 9;
            #pragma unroll
            for (int ky = 0; ky < 3; ++ky) {
                int gy = y + ky - 1;
                if ((unsigned)gy >= 64u) continue;
                const float* xr = xc + gy * 64;
                const float* wk = wc + ky * 3;
                #pragma unroll
                for (int kx = 0; kx < 3; ++kx) {
                    int gx = xp + kx - 1;
                    if ((unsigned)gx >= 64u) continue;
                    z += (double)xr[gx] * (double)wk[kx];
                }
            }
        }
        // segmented reduce within each 4-lane t-group (root = lane 4t)
        z += __shfl_down_sync(0xffffffffu, z, 2);
        z += __shfl_down_sync(0xffffffffu, z, 1);

        // lane 0 gathers z_t and runs the LIF scan
        float v = 0.0f;
        for (int t = 0; t < TT; ++t) {
            double zt = __shfl_sync(0xffffffffu, z, t * 4);
            if (lane == 0) {
                float zf = (float)zt;
                v = v + (zf - v) * 0.5f;
                float s = (v >= 1.0f) ? 1.0f : 0.0f;
                v = (v >= 1.0f) ? 0.0f : v;
                out[((size_t)(t * BB + b) * 64 + co) * 4096 + y * 64 + xp] = s;
            }
        }
    }

    __syncthreads();
    if (threadIdx.x == 0) {
        __threadfence();
        int d = atomicAdd(&g_done, 1);
        if (d == (int)gridDim.x - 1) {
            g_cnt = 0;
            g_done = 0;
            __threadfence();
        }
    }
}

extern "C" void kernel_launch(void* const* d_in, const int* in_sizes, int n_in,
                              void* d_out, int out_size) {
    const float* x  = (const float*)d_in[0];
    const float* w  = (const float*)d_in[1];
    float* out      = (float*)d_out;
    cudaFuncSetAttribute(snn_conv_lif_kernel,
                         cudaFuncAttributeMaxDynamicSharedMemorySize, SMEM_BYTES);
    snn_conv_lif_kernel<<<NSM, 256, SMEM_BYTES>>>(x, w, out);
    fix_kernel<<<256, 256>>>(x, w, out);
}

// round 16
// speedup vs baseline: 1.3914x; 1.0881x over previous
#include <cuda_runtime.h>
#include <cuda_fp16.h>
#include <cstdint>
#include <math.h>

// Fused 3x3 conv via fp16 m16n8k16 MMA with exact Dekker split (3 products,
// fp32-class z) + LIF scan + flag-and-fix.
//
// Round-15: main kernel byte-identical to the 451us round-11 artifact
// (mainloop is a fragile local optimum; every perturbation regressed).
// Fixer split into two kernels: warp-per-(flag,timestep) fp64 z compute
// (same summation order as the validated serial fixer -> bitwise-identical
// z) into device scratch, then a tiny per-flag LIF-scan kernel. Cuts the
// fixer's 8x serial conv chain to one conv of latency.
//
// x: [T=8, B=16, Cin=64, 64, 64] f32   w: [64, 64, 3, 3] f32
// out: spikes [8, 16, 64, 64, 64] f32

#define TT 8
#define BB 16
#define NSM 148
#define NUNITS 1024          // 16 b x 64 tiles (16 y-groups x 4 x-groups)
#define PFN 27               // 64*108 / 256 prefetch elements per thread

// word (4B) offsets in dynamic smem
#define WPLANE_WORDS (576 * 36)           // [tap*64+co][ci/2] f16x2, pitch 36
#define INPLANE_WORDS (108 * 36)          // [y*18+x][ci/2], 6 rows x 18 cols
#define SM_WH 0
#define SM_WL WPLANE_WORDS
#define SM_INH (2 * WPLANE_WORDS)
#define SM_INL (2 * WPLANE_WORDS + INPLANE_WORDS)
#define SMEM_WORDS (2 * WPLANE_WORDS + 2 * INPLANE_WORDS)
#define SMEM_BYTES (SMEM_WORDS * 4)       // 196,992 B

#define FLAG_CAP 131072
#define FLAG_DELTA 4e-5f

__device__ int g_cnt;    // zeroed at module load; reset by fix_scan_kernel
__device__ int g_done;
__device__ int g_idx[FLAG_CAP];
__device__ double g_z[FLAG_CAP * 8];   // per-flag per-timestep exact z

__device__ __forceinline__ void mma16(float* c, const uint32_t* a,
                                      uint32_t b0, uint32_t b1) {
    asm volatile(
        "mma.sync.aligned.m16n8k16.row.col.f32.f16.f16.f32 "
        "{%0,%1,%2,%3}, {%4,%5,%6,%7}, {%8,%9}, {%0,%1,%2,%3};"
        : "+f"(c[0]), "+f"(c[1]), "+f"(c[2]), "+f"(c[3])
        : "r"(a[0]), "r"(a[1]), "r"(a[2]), "r"(a[3]), "r"(b0), "r"(b1));
}
__device__ __forceinline__ void push_flag(int enc) {
    int i = atomicAdd(&g_cnt, 1);
    if (i < FLAG_CAP) g_idx[i] = enc;
}

__global__ __launch_bounds__(256, 1)
void snn_conv_lif_kernel(const float* __restrict__ x,
                         const float* __restrict__ w,
                         float* __restrict__ out)
{
    extern __shared__ uint32_t smem[];
    uint32_t* whU  = smem + SM_WH;
    uint32_t* wlU  = smem + SM_WL;
    uint32_t* inhU = smem + SM_INH;
    uint32_t* inlU = smem + SM_INL;
    __half* whH  = reinterpret_cast<__half*>(whU);
    __half* wlH  = reinterpret_cast<__half*>(wlU);
    __half* inhH = reinterpret_cast<__half*>(inhU);
    __half* inlH = reinterpret_cast<__half*>(inlU);

    const int tid  = threadIdx.x;
    const int wid  = tid >> 5;
    const int lane = tid & 31;
    const int gid  = lane >> 2;          // 0..7
    const int tig  = lane & 3;           // 0..3

    const int warpM = wid & 3;           // 1 y-row of 16 px
    const int warpN = wid >> 2;          // 32-co half

    // ---- stage weights ONCE: hi/lo half-planes [tap*64+co][ci] ----
    for (int idx = tid; idx < 64 * 64 * 9; idx += 256) {
        int co  = idx / 576;
        int r   = idx % 576;
        int ci  = r / 9;
        int tap = r % 9;
        float f = w[idx];
        __half h = __float2half_rn(f);
        __half l = __float2half_rn(f - __half2float(h));
        int hidx = (tap * 64 + co) * 72 + ci;   // pitch 72 halves
        whH[hidx] = h;
        wlH[hidx] = l;
    }

    // ---- persistent loop over work units ----
    for (int u = blockIdx.x; u < NUNITS; u += NSM) {
        const int b    = u >> 6;
        const int tile = u & 63;
        const int ty0  = (tile >> 2) * 4;    // 16 y-groups of 4 rows
        const int tx0  = (tile & 3) * 16;    // 4 x-groups of 16 cols

        float v[16];
        #pragma unroll
        for (int i = 0; i < 16; ++i) v[i] = 0.0f;

        // ---- direct stage for t=0 (also fences weights on first unit) ----
        {
            const float* xt = x + (size_t)b * (64 * 64 * 64);
            #pragma unroll
            for (int k = 0; k < PFN; ++k) {
                int i   = tid + k * 256;
                int ci  = i / 108;
                int pix = i - ci * 108;
                int tyi = pix / 18;
                int txi = pix - tyi * 18;
                int gy = ty0 + tyi - 1;
                int gx = tx0 + txi - 1;
                float val = 0.0f;
                if ((unsigned)gy < 64u && (unsigned)gx < 64u)
                    val = xt[ci * 4096 + gy * 64 + gx];
                __half h = __float2half_rn(val);
                __half l = __float2half_rn(val - __half2float(h));
                inhH[pix * 72 + ci] = h;
                inlH[pix * 72 + ci] = l;
            }
        }
        __syncthreads();

        for (int t = 0; t < TT; ++t) {
            // ---- prefetch NEXT timestep's inputs into registers ----
            float pf[PFN];
            if (t < TT - 1) {
                const float* xn = x + (size_t)((t + 1) * BB + b) * (64 * 64 * 64);
                #pragma unroll
                for (int k = 0; k < PFN; ++k) {
                    int i   = tid + k * 256;
                    int ci  = i / 108;
                    int pix = i - ci * 108;
                    int tyi = pix / 18;
                    int txi = pix - tyi * 18;
                    int gy = ty0 + tyi - 1;
                    int gx = tx0 + txi - 1;
                    float val = 0.0f;
                    if ((unsigned)gy < 64u && (unsigned)gx < 64u)
                        val = xn[ci * 4096 + gy * 64 + gx];
                    pf[k] = val;
                }
            }

            // ---- implicit GEMM, fp16 split x3: acc[nt*4 + r] ----
            float acc[16];
            #pragma unroll
            for (int i = 0; i < 16; ++i) acc[i] = 0.0f;

            #pragma unroll 1
            for (int tap = 0; tap < 9; ++tap) {
                const int ky = tap / 3, kx = tap % 3;

                #pragma unroll
                for (int kb = 0; kb < 4; ++kb) {       // 16 ci per k-tile
                    const int pix = (warpM + ky) * 18 + kx + gid;
                    const int pa  = pix * 36 + kb * 8 + tig;
                    const int pb  = pa + 8 * 36;       // pixel x + 8
                    uint32_t ah[4], al[4];
                    ah[0] = inhU[pa];
                    ah[1] = inhU[pb];
                    ah[2] = inhU[pa + 4];
                    ah[3] = inhU[pb + 4];
                    al[0] = inlU[pa];
                    al[1] = inlU[pb];
                    al[2] = inlU[pa + 4];
                    al[3] = inlU[pb + 4];
                    #pragma unroll
                    for (int nt = 0; nt < 4; ++nt) {
                        const int co = warpN * 32 + nt * 8 + gid;
                        const int wi = (tap * 64 + co) * 36 + kb * 8 + tig;
                        uint32_t bh0 = whU[wi], bh1 = whU[wi + 4];
                        uint32_t bl0 = wlU[wi], bl1 = wlU[wi + 4];
                        mma16(&acc[nt * 4], ah, bh0, bh1);
                        mma16(&acc[nt * 4], al, bh0, bh1);
                        mma16(&acc[nt * 4], ah, bl0, bl1);
                    }
                }
            }

            // ---- LIF update + near-threshold flagging + spike store ----
            float* obase = out + (size_t)(t * BB + b) * (64 * 4096);
            const int yg = ty0 + warpM;
            #pragma unroll
            for (int nt = 0; nt < 4; ++nt) {
                #pragma unroll
                for (int r = 0; r < 4; ++r) {
                    const int co = warpN * 32 + nt * 8 + 2 * tig + (r & 1);
                    const int xg = tx0 + gid + ((r & 2) ? 8 : 0);
                    const int vi = nt * 4 + r;
                    float z = acc[vi];
                    float vv = v[vi];
                    vv = vv + (z - vv) * 0.5f;   // TAU=2, reference op order
                    if (fabsf(vv - 1.0f) < FLAG_DELTA)
                        push_flag((((b * 64 + co) * 64 + yg) * 64) + xg);
                    float s = (vv >= 1.0f) ? 1.0f : 0.0f;
                    v[vi] = (vv >= 1.0f) ? 0.0f : vv;
                    obase[(size_t)co * 4096 + yg * 64 + xg] = s;
                }
            }

            __syncthreads();   // all MMA reads of input planes done

            // ---- commit prefetched inputs (convert + split + STS) ----
            if (t < TT - 1) {
                #pragma unroll
                for (int k = 0; k < PFN; ++k) {
                    int i   = tid + k * 256;
                    int ci  = i / 108;
                    int pix = i - ci * 108;
                    float val = pf[k];
                    __half h = __float2half_rn(val);
                    __half l = __float2half_rn(val - __half2float(h));
                    inhH[pix * 72 + ci] = h;
                    inlH[pix * 72 + ci] = l;
                }
                __syncthreads();
            }
        }
    }
}

// ---------------- fix stage 1: warp-per-(flag, timestep) z compute --------
// Same summation order as the validated serial fixer (lane = 2 ci, 18 taps,
// shuffle tree-reduce) -> bitwise-identical z. Lane 0 stores to g_z.
__global__ void fix_z_kernel(const float* __restrict__ x,
                             const float* __restrict__ w)
{
    int n = g_cnt;
    if (n > FLAG_CAP) n = FLAG_CAP;
    const int ntask = n * 8;
    const int lane = threadIdx.x & 31;
    const int wtid = (blockIdx.x * blockDim.x + threadIdx.x) >> 5;
    const int nw   = (gridDim.x * blockDim.x) >> 5;
    const int ci0  = lane * 2;

    for (int task = wtid; task < ntask; task += nw) {
        const int i = task >> 3;
        const int t = task & 7;
        int e = g_idx[i];
        int xp = e & 63;
        int y  = (e >> 6) & 63;
        int co = (e >> 12) & 63;
        int b  = e >> 18;
        const float* wr = w + co * 576;
        const float* xt = x + (size_t)(t * BB + b) * (64 * 64 * 64);

        double z = 0.0;
        #pragma unroll
        for (int cc = 0; cc < 2; ++cc) {
            int ci = ci0 + cc;
            #pragma unroll
            for (int ky = 0; ky < 3; ++ky) {
                int gy = y + ky - 1;
                if ((unsigned)gy >= 64u) continue;
                const float* xr = xt + ci * 4096 + gy * 64;
                const float* wk = wr + ci * 9 + ky * 3;
                #pragma unroll
                for (int kx = 0; kx < 3; ++kx) {
                    int gx = xp + kx - 1;
                    if ((unsigned)gx >= 64u) continue;
                    z += (double)xr[gx] * (double)wk[kx];
                }
            }
        }
        #pragma unroll
        for (int off = 16; off > 0; off >>= 1)
            z += __shfl_down_sync(0xffffffffu, z, off);
        if (lane == 0) g_z[task] = z;
    }
}

// ---------------- fix stage 2: per-flag LIF scan + store ------------------
// One thread per flag. Reference-identical fp32 LIF over the 8 exact z's.
// Last block resets g_cnt/g_done so the captured graph is replay-safe.
__global__ void fix_scan_kernel(float* __restrict__ out)
{
    int n = g_cnt;
    if (n > FLAG_CAP) n = FLAG_CAP;
    for (int i = blockIdx.x * blockDim.x + threadIdx.x; i < n;
         i += gridDim.x * blockDim.x) {
        int e = g_idx[i];
        int xp = e & 63;
        int y  = (e >> 6) & 63;
        int co = (e >> 12) & 63;
        int b  = e >> 18;
        float v = 0.0f;
        #pragma unroll
        for (int t = 0; t < TT; ++t) {
            float zf = (float)g_z[i * 8 + t];
            v = v + (zf - v) * 0.5f;
            float s = (v >= 1.0f) ? 1.0f : 0.0f;
            v = (v >= 1.0f) ? 0.0f : v;
            out[((size_t)(t * BB + b) * 64 + co) * 4096 + y * 64 + xp] = s;
        }
    }

    __syncthreads();
    if (threadIdx.x == 0) {
        __threadfence();
        int d = atomicAdd(&g_done, 1);
        if (d == (int)gridDim.x - 1) {
            g_cnt = 0;
            g_done = 0;
            __threadfence();
        }
    }
}

extern "C" void kernel_launch(void* const* d_in, const int* in_sizes, int n_in,
                              void* d_out, int out_size) {
    const float* x  = (const float*)d_in[0];
    const float* w  = (const float*)d_in[1];
    float* out      = (float*)d_out;
    cudaFuncSetAttribute(snn_conv_lif_kernel,
                         cudaFuncAttributeMaxDynamicSharedMemorySize, SMEM_BYTES);
    snn_conv_lif_kernel<<<NSM, 256, SMEM_BYTES>>>(x, w, out);
    fix_z_kernel<<<256, 256>>>(x, w);
    fix_scan_kernel<<<64, 256>>>(out);
}